// round 9
// baseline (speedup 1.0000x reference)
#include <cuda_runtime.h>
#include <cstdint>

#define HIDDEN   256
#define LATENT   128
#define VOCAB    32000
#define MAX_LEN  64
#define MAX_STEPS 128
#define N_NODES  511

// ------------------- device scratch -------------------
__device__ __align__(16) float g_h[N_NODES * HIDDEN];
__device__ __align__(16) float g_W2T[HIDDEN * HIDDEN];   // [k][j], rows 1..256 of W2
__device__ __align__(16) float g_WpCT[HIDDEN * HIDDEN];  // [m][j]
__device__ __align__(16) float g_bpC[HIDDEN];
__device__ __align__(16) float g_H[MAX_STEPS * HIDDEN];
__device__ __align__(16) float g_CO[MAX_STEPS * HIDDEN];
__device__ int g_leafRows[MAX_STEPS];
__device__ int g_parRows[MAX_STEPS];
__device__ int g_nLeaf;
__device__ int g_nPar;
__device__ int g_nOut;

// ------------------- PTX helpers -------------------
__device__ __forceinline__ uint32_t s2u(const void* p) {
    uint32_t a;
    asm("{ .reg .u64 t; cvta.to.shared.u64 t, %1; cvt.u32.u64 %0, t; }" : "=r"(a) : "l"(p));
    return a;
}
__device__ __forceinline__ uint32_t ctarank() {
    uint32_t r; asm("mov.u32 %0, %%cluster_ctarank;" : "=r"(r)); return r;
}
__device__ __forceinline__ void st_cluster_f(uint32_t saddr, uint32_t rank, float v) {
    uint32_t ra;
    asm volatile("mapa.shared::cluster.u32 %0, %1, %2;" : "=r"(ra) : "r"(saddr), "r"(rank));
    asm volatile("st.shared::cluster.b32 [%0], %1;" :: "r"(ra), "r"(__float_as_uint(v)) : "memory");
}
__device__ __forceinline__ void mbar_init(uint32_t a, uint32_t cnt) {
    asm volatile("mbarrier.init.shared.b64 [%0], %1;" :: "r"(a), "r"(cnt) : "memory");
}
__device__ __forceinline__ void mbar_arrive_cluster(uint32_t a, uint32_t r) {
    asm volatile("{ .reg .b32 ra; mapa.shared::cluster.u32 ra, %0, %1;\n\t"
                 "mbarrier.arrive.release.cluster.shared::cluster.b64 _, [ra]; }"
                 :: "r"(a), "r"(r) : "memory");
}
__device__ __forceinline__ void mbar_wait_cluster(uint32_t a, uint32_t parity) {
    uint32_t done;
    asm volatile("{ .reg .pred p; mbarrier.try_wait.parity.acquire.cluster.shared::cta.b64 p, [%1], %2; selp.b32 %0,1,0,p; }"
                 : "=r"(done) : "r"(a), "r"(parity) : "memory");
    if (!done) {
        asm volatile("{ .reg .pred P1;\n"
                     "WL%=:\n\t"
                     "mbarrier.try_wait.parity.acquire.cluster.shared::cta.b64 P1, [%0], %1, 0x989680;\n\t"
                     "@P1 bra.uni WD%=;\n\t"
                     "bra.uni WL%=;\n"
                     "WD%=:\n}"
                     :: "r"(a), "r"(parity) : "memory");
    }
}
#define CLUSTER_SYNC() do { \
    asm volatile("barrier.cluster.arrive.aligned;" ::: "memory"); \
    asm volatile("barrier.cluster.wait.aligned;" ::: "memory"); \
} while (0)

// f32x2 packed helpers
__device__ __forceinline__ unsigned long long pack2(float v) {
    unsigned long long r;
    asm("mov.b64 %0, {%1, %1};" : "=l"(r) : "r"(__float_as_uint(v)));
    return r;
}
__device__ __forceinline__ void ffma2(unsigned long long& acc,
                                      unsigned long long a, unsigned long long b) {
    asm("fma.rn.f32x2 %0, %1, %2, %0;" : "+l"(acc) : "l"(a), "l"(b));
}

// ------------------- enc level d=7 + prep (grid (64,9)) -------------------
// y<8: encoder level-7 slice; y==8: prep (blocks 0-31 fold WpC, 32-63 W2T)
__global__ void __launch_bounds__(256) enc7_prep(
    const float* __restrict__ embed, const int* __restrict__ values,
    const float* __restrict__ Wpar, const float* __restrict__ bpar,
    const float* __restrict__ Wp, const float* __restrict__ W2,
    const float* __restrict__ b2, const float* __restrict__ bp)
{
    __shared__ __align__(16) float sm[2304];
    int t = threadIdx.x;
    if (blockIdx.y == 8) {
        int pb = blockIdx.x;
        if (pb >= 32) {
            int base = (pb - 32) * 2048;
            #pragma unroll
            for (int it = 0; it < 8; it++) {
                int i = base + it * 256 + t;
                int j = i >> 8, k = i & 255;
                g_W2T[k * 256 + j] = W2[(1 + j) * 256 + k];
            }
            return;
        }
        float (*wrows)[256] = reinterpret_cast<float (*)[256]>(sm);
        float* b2s = sm + 8 * 256;
        int j0 = pb * 8;
        for (int i = t; i < 8 * 256; i += 256) {
            int r = i >> 8, k = i & 255;
            wrows[r][k] = Wp[(long)(VOCAB + j0 + r) * HIDDEN + k];
        }
        b2s[t] = b2[1 + t];
        __syncthreads();
        float acc[8] = {0.f, 0.f, 0.f, 0.f, 0.f, 0.f, 0.f, 0.f};
        for (int k = 0; k < 256; k++) {
            float w2v = W2[(1 + k) * 256 + t];
            #pragma unroll
            for (int r = 0; r < 8; r++) acc[r] += wrows[r][k] * w2v;
        }
        #pragma unroll
        for (int r = 0; r < 8; r++) g_WpCT[t * 256 + j0 + r] = acc[r];
        int w = t >> 5, l = t & 31;
        float p = wrows[w][l] * b2s[l] + wrows[w][l + 32] * b2s[l + 32]
                + wrows[w][l + 64] * b2s[l + 64] + wrows[w][l + 96] * b2s[l + 96]
                + wrows[w][l + 128] * b2s[l + 128] + wrows[w][l + 160] * b2s[l + 160]
                + wrows[w][l + 192] * b2s[l + 192] + wrows[w][l + 224] * b2s[l + 224];
        #pragma unroll
        for (int o = 16; o; o >>= 1) p += __shfl_xor_sync(0xFFFFFFFFu, p, o);
        if (l == 0) g_bpC[j0 + w] = p + bp[VOCAB + j0 + w];
        return;
    }
    // ---- encoder level 7 ----
    float (*cat)[768] = reinterpret_cast<float (*)[768]>(sm);
    int n0 = 127 + blockIdx.x * 2;
    #pragma unroll
    for (int ln = 0; ln < 2; ln++) {
        int n = n0 + ln;
        cat[ln][t]       = embed[(long)values[n] * 256 + t];
        cat[ln][256 + t] = embed[(long)values[2 * n + 1] * 256 + t];
        cat[ln][512 + t] = embed[(long)values[2 * n + 2] * 256 + t];
    }
    __syncthreads();
    int w = t >> 5, l = t & 31;
    int j0 = blockIdx.y * 32 + w * 4;
    const float4* W4 = reinterpret_cast<const float4*>(Wpar);
    const float4* c0 = reinterpret_cast<const float4*>(cat[0]);
    const float4* c1 = reinterpret_cast<const float4*>(cat[1]);
    float a0 = 0.f, a1 = 0.f, a2 = 0.f, a3 = 0.f;
    float b0 = 0.f, b1 = 0.f, b2v = 0.f, b3 = 0.f;
    #pragma unroll
    for (int it = 0; it < 6; it++) {
        int ki = it * 32 + l;
        float4 w0 = W4[(long)(j0 + 0) * 192 + ki];
        float4 w1 = W4[(long)(j0 + 1) * 192 + ki];
        float4 w2 = W4[(long)(j0 + 2) * 192 + ki];
        float4 w3 = W4[(long)(j0 + 3) * 192 + ki];
        float4 v0 = c0[ki];
        float4 v1 = c1[ki];
        a0 += w0.x * v0.x + w0.y * v0.y + w0.z * v0.z + w0.w * v0.w;
        a1 += w1.x * v0.x + w1.y * v0.y + w1.z * v0.z + w1.w * v0.w;
        a2 += w2.x * v0.x + w2.y * v0.y + w2.z * v0.z + w2.w * v0.w;
        a3 += w3.x * v0.x + w3.y * v0.y + w3.z * v0.z + w3.w * v0.w;
        b0 += w0.x * v1.x + w0.y * v1.y + w0.z * v1.z + w0.w * v1.w;
        b1 += w1.x * v1.x + w1.y * v1.y + w1.z * v1.z + w1.w * v1.w;
        b2v += w2.x * v1.x + w2.y * v1.y + w2.z * v1.z + w2.w * v1.w;
        b3 += w3.x * v1.x + w3.y * v1.y + w3.z * v1.z + w3.w * v1.w;
    }
    #pragma unroll
    for (int o = 16; o; o >>= 1) {
        a0 += __shfl_xor_sync(0xFFFFFFFFu, a0, o);
        a1 += __shfl_xor_sync(0xFFFFFFFFu, a1, o);
        a2 += __shfl_xor_sync(0xFFFFFFFFu, a2, o);
        a3 += __shfl_xor_sync(0xFFFFFFFFu, a3, o);
        b0 += __shfl_xor_sync(0xFFFFFFFFu, b0, o);
        b1 += __shfl_xor_sync(0xFFFFFFFFu, b1, o);
        b2v += __shfl_xor_sync(0xFFFFFFFFu, b2v, o);
        b3 += __shfl_xor_sync(0xFFFFFFFFu, b3, o);
    }
    if (l == 0) {
        float bb0 = bpar[j0], bb1 = bpar[j0 + 1], bb2 = bpar[j0 + 2], bb3 = bpar[j0 + 3];
        g_h[n0 * 256 + j0 + 0] = a0 + bb0;
        g_h[n0 * 256 + j0 + 1] = a1 + bb1;
        g_h[n0 * 256 + j0 + 2] = a2 + bb2;
        g_h[n0 * 256 + j0 + 3] = a3 + bb3;
        g_h[(n0 + 1) * 256 + j0 + 0] = b0 + bb0;
        g_h[(n0 + 1) * 256 + j0 + 1] = b1 + bb1;
        g_h[(n0 + 1) * 256 + j0 + 2] = b2v + bb2;
        g_h[(n0 + 1) * 256 + j0 + 3] = b3 + bb3;
    }
}

// ------------------- encoder level (d=6,5): 2 nodes x 32 outputs ------------
__global__ void __launch_bounds__(256) enc_level(
    const float* __restrict__ embed, const int* __restrict__ values,
    const float* __restrict__ Wpar, const float* __restrict__ bpar,
    int first)
{
    __shared__ __align__(16) float cat[2][768];
    int t = threadIdx.x;
    int n0 = first + blockIdx.x * 2;
    #pragma unroll
    for (int ln = 0; ln < 2; ln++) {
        int n = n0 + ln;
        cat[ln][t]       = embed[(long)values[n] * 256 + t];
        cat[ln][256 + t] = g_h[(2 * n + 1) * 256 + t];
        cat[ln][512 + t] = g_h[(2 * n + 2) * 256 + t];
    }
    __syncthreads();
    int w = t >> 5, l = t & 31;
    int j0 = blockIdx.y * 32 + w * 4;
    const float4* W4 = reinterpret_cast<const float4*>(Wpar);
    const float4* c0 = reinterpret_cast<const float4*>(cat[0]);
    const float4* c1 = reinterpret_cast<const float4*>(cat[1]);
    float a0 = 0.f, a1 = 0.f, a2 = 0.f, a3 = 0.f;
    float b0 = 0.f, b1 = 0.f, b2v = 0.f, b3 = 0.f;
    #pragma unroll
    for (int it = 0; it < 6; it++) {
        int ki = it * 32 + l;
        float4 w0 = W4[(long)(j0 + 0) * 192 + ki];
        float4 w1 = W4[(long)(j0 + 1) * 192 + ki];
        float4 w2 = W4[(long)(j0 + 2) * 192 + ki];
        float4 w3 = W4[(long)(j0 + 3) * 192 + ki];
        float4 v0 = c0[ki];
        float4 v1 = c1[ki];
        a0 += w0.x * v0.x + w0.y * v0.y + w0.z * v0.z + w0.w * v0.w;
        a1 += w1.x * v0.x + w1.y * v0.y + w1.z * v0.z + w1.w * v0.w;
        a2 += w2.x * v0.x + w2.y * v0.y + w2.z * v0.z + w2.w * v0.w;
        a3 += w3.x * v0.x + w3.y * v0.y + w3.z * v0.z + w3.w * v0.w;
        b0 += w0.x * v1.x + w0.y * v1.y + w0.z * v1.z + w0.w * v1.w;
        b1 += w1.x * v1.x + w1.y * v1.y + w1.z * v1.z + w1.w * v1.w;
        b2v += w2.x * v1.x + w2.y * v1.y + w2.z * v1.z + w2.w * v1.w;
        b3 += w3.x * v1.x + w3.y * v1.y + w3.z * v1.z + w3.w * v1.w;
    }
    #pragma unroll
    for (int o = 16; o; o >>= 1) {
        a0 += __shfl_xor_sync(0xFFFFFFFFu, a0, o);
        a1 += __shfl_xor_sync(0xFFFFFFFFu, a1, o);
        a2 += __shfl_xor_sync(0xFFFFFFFFu, a2, o);
        a3 += __shfl_xor_sync(0xFFFFFFFFu, a3, o);
        b0 += __shfl_xor_sync(0xFFFFFFFFu, b0, o);
        b1 += __shfl_xor_sync(0xFFFFFFFFu, b1, o);
        b2v += __shfl_xor_sync(0xFFFFFFFFu, b2v, o);
        b3 += __shfl_xor_sync(0xFFFFFFFFu, b3, o);
    }
    if (l == 0) {
        float bb0 = bpar[j0], bb1 = bpar[j0 + 1], bb2 = bpar[j0 + 2], bb3 = bpar[j0 + 3];
        g_h[n0 * 256 + j0 + 0] = a0 + bb0;
        g_h[n0 * 256 + j0 + 1] = a1 + bb1;
        g_h[n0 * 256 + j0 + 2] = a2 + bb2;
        g_h[n0 * 256 + j0 + 3] = a3 + bb3;
        g_h[(n0 + 1) * 256 + j0 + 0] = b0 + bb0;
        g_h[(n0 + 1) * 256 + j0 + 1] = b1 + bb1;
        g_h[(n0 + 1) * 256 + j0 + 2] = b2v + bb2;
        g_h[(n0 + 1) * 256 + j0 + 3] = b3 + bb3;
    }
}

// ------------------- decoder cluster: tree tail + latent + control loop -------
#define DSM_W1    0                      // [k 128][j' 32]     4096
#define DSM_WPC   4096                   // [m 256][j' 32]     8192
#define DSM_STACK 12288                  // [64][128]          8192
#define DSM_HB    20480                  // hmid dbl buf       512
#define DSM_LLRL  20992                  // 256
#define DSM_PP    21248                  // 16
#define DSM_RED   21264                  // 256
#define DSM_HLOC  21520                  // h nodes 0..30      7936
#define DSM_CAT   29456                  // 768
#define DSM_FLOATS 30224
#define DSM_MBAR_BYTE (DSM_FLOATS * 4)
#define DEC_SMEM_BYTES (DSM_MBAR_BYTE + 16)

__global__ void __cluster_dims__(8, 1, 1) __launch_bounds__(256, 1)
dec_cluster(const float* __restrict__ W1, const float* __restrict__ b1,
            const float* __restrict__ W2, const float* __restrict__ b2,
            const float* __restrict__ Wpar, const float* __restrict__ bpar,
            const float* __restrict__ embed, const int* __restrict__ values,
            const float* __restrict__ Wmu, const float* __restrict__ bmu,
            const float* __restrict__ Wlv, const float* __restrict__ blv,
            const float* __restrict__ eps, float* __restrict__ out)
{
    extern __shared__ float S[];
    float* W1s   = S + DSM_W1;
    float* WpCs  = S + DSM_WPC;
    float* stack = S + DSM_STACK;
    float* hb2   = S + DSM_HB;
    float* llrl  = S + DSM_LLRL;
    float* pp    = S + DSM_PP;
    float* red   = S + DSM_RED;
    float* hloc  = S + DSM_HLOC;   // [31][256]
    float* cat   = S + DSM_CAT;    // [768]
    uint32_t smem_u = s2u(S);
    uint32_t mbarA = smem_u + DSM_MBAR_BYTE;
    uint32_t mbarB = mbarA + 8;

    int t = threadIdx.x;
    int j2 = t & 31, kg = t >> 5;
    uint32_t rank = ctarank();
    int rowbase = (int)rank * 32;

    // Wpar slice into registers: thread owns row (rowbase+j2), k in [kg*96, kg*96+96)
    float4 wreg[24];
    {
        const float4* wsrc = reinterpret_cast<const float4*>(
            Wpar + (long)(rowbase + j2) * 768) + kg * 24;
        #pragma unroll
        for (int i = 0; i < 24; i++) wreg[i] = wsrc[i];
    }

    for (int i = t; i < 4096; i += 256) {
        int jp = i >> 7, k = i & 127;
        W1s[k * 32 + jp] = W1[(rowbase + jp) * 128 + k];
    }
    for (int i = t; i < 8192; i += 256) {
        int m = i >> 5, jp = i & 31;
        WpCs[i] = g_WpCT[m * 256 + rowbase + jp];
    }
    for (int i = t; i < 8192; i += 256) stack[i] = 0.f;
    float b1v   = (t < 32) ? b1[rowbase + t] : 0.f;
    float bparv = (t < 32) ? bpar[rowbase + t] : 0.f;
    float bpcv  = (t < 32) ? g_bpC[rowbase + t] : 0.f;
    float w2r0v = (t < 32) ? W2[rowbase + t] : 0.f;
    float b20   = b2[0];
    if (t == 0) { mbar_init(mbarA, 256); mbar_init(mbarB, 256); }
    __syncthreads();
    CLUSTER_SYNC();

    // ---- tree levels d=4..0 (nodes 15..30, 7..14, 3..6, 1..2, 0) ----
    for (int d = 4; d >= 0; d--) {
        int first = (1 << d) - 1, cnt = 1 << d;
        for (int n = first; n < first + cnt; n++) {
            // build cat = [emb | h_left | h_right]
            int li = 2 * n + 1, ri = 2 * n + 2;
            const float* eb = embed + (long)values[n] * 256;
            {
                int i = t;
                cat[i] = eb[i];
                cat[256 + i] = (li >= 31) ? g_h[li * 256 + i] : hloc[li * 256 + i];
                cat[512 + i] = (ri >= 31) ? g_h[ri * 256 + i] : hloc[ri * 256 + i];
            }
            __syncthreads();
            float a0 = 0.f, a1 = 0.f, a2 = 0.f, a3 = 0.f;
            const float4* xs = reinterpret_cast<const float4*>(cat) + kg * 24;
            #pragma unroll
            for (int i = 0; i < 24; i++) {
                float4 x = xs[i];
                a0 += wreg[i].x * x.x;
                a1 += wreg[i].y * x.y;
                a2 += wreg[i].z * x.z;
                a3 += wreg[i].w * x.w;
            }
            red[kg * 32 + j2] = (a0 + a1) + (a2 + a3);
            __syncthreads();
            if (t < 32) {
                float v = bparv;
                #pragma unroll
                for (int g = 0; g < 8; g++) v += red[g * 32 + t];
                uint32_t sa = s2u(&hloc[n * 256 + rowbase + t]);
                #pragma unroll
                for (int r = 0; r < 8; r++) st_cluster_f(sa, (uint32_t)r, v);
            }
            __syncthreads();
        }
        CLUSTER_SYNC();   // level's hloc broadcasts visible everywhere
    }

    // ---- latent head (redundant per CTA, deterministic) ----
    {
        const float* root = hloc;        // node 0
        float a;
        if (t < 128) {
            a = bmu[t];
            const float* wr = Wmu + t * 256;
            float s0 = 0.f, s1 = 0.f, s2 = 0.f, s3 = 0.f;
            #pragma unroll 4
            for (int k = 0; k < 256; k += 4) {
                s0 += wr[k + 0] * root[k + 0];
                s1 += wr[k + 1] * root[k + 1];
                s2 += wr[k + 2] * root[k + 2];
                s3 += wr[k + 3] * root[k + 3];
            }
            a += (s0 + s1) + (s2 + s3);
        } else {
            int j = t - 128;
            a = blv[j];
            const float* wr = Wlv + j * 256;
            float s0 = 0.f, s1 = 0.f, s2 = 0.f, s3 = 0.f;
            #pragma unroll 4
            for (int k = 0; k < 256; k += 4) {
                s0 += wr[k + 0] * root[k + 0];
                s1 += wr[k + 1] * root[k + 1];
                s2 += wr[k + 2] * root[k + 2];
                s3 += wr[k + 3] * root[k + 3];
            }
            a += (s0 + s1) + (s2 + s3);
        }
        cat[t] = a;                      // mu in cat[0:128), logvar in cat[128:256)
        if (rank == 0) out[(long)MAX_STEPS * VOCAB + t] = a;
        __syncthreads();
        if (t < 128) stack[t] = cat[t] + eps[t] * expf(0.5f * cat[128 + t]);
        __syncthreads();
    }

    // ---- sequential decoder control loop ----
    int sp = 1, op = 0, nl = 0, np = 0;
    uint32_t parA = 0, parB = 0;
    for (int step = 0; step < MAX_STEPS && sp > 0; step++) {
        int idx = sp - 1;
        float* hb = hb2 + (step & 1) * 256;
        const float* x = stack + idx * 128;

        {
            float acc = 0.f;
            int k0 = kg * 16;
            #pragma unroll
            for (int kk = 0; kk < 16; kk++)
                acc += W1s[(k0 + kk) * 32 + j2] * x[k0 + kk];
            red[kg * 32 + j2] = acc;
        }
        __syncthreads();
        if (t < 32) {
            float v = b1v;
            #pragma unroll
            for (int g = 0; g < 8; g++) v += red[g * 32 + t];
            v = v > 0.f ? v : 0.2f * v;
            uint32_t sa = s2u(&hb[rowbase + t]);
            #pragma unroll
            for (int r = 0; r < 8; r++) st_cluster_f(sa, (uint32_t)r, v);
            g_H[op * 256 + rowbase + t] = v;
            float p = w2r0v * v;
            #pragma unroll
            for (int o = 16; o; o >>= 1) p += __shfl_xor_sync(0xFFFFFFFFu, p, o);
            if (t == 0) {
                uint32_t sb = s2u(&pp[(step & 1) * 8 + rank]);
                #pragma unroll
                for (int r = 0; r < 8; r++) st_cluster_f(sb, (uint32_t)r, p);
            }
            #pragma unroll
            for (int r = 0; r < 8; r++) mbar_arrive_cluster(mbarA, (uint32_t)r);
        }
        mbar_wait_cluster(mbarA, parA);
        parA ^= 1;
        const float* ppb = pp + (step & 1) * 8;
        float co0 = b20 + ((ppb[0] + ppb[1]) + (ppb[2] + ppb[3]))
                        + ((ppb[4] + ppb[5]) + (ppb[6] + ppb[7]));
        bool parent = (co0 > 0.f) && (idx <= MAX_LEN - 2);

        if (parent) {
            float dd = 0.f;
            int m0 = kg * 32;
            #pragma unroll
            for (int mm = 0; mm < 32; mm++)
                dd += WpCs[(m0 + mm) * 32 + j2] * hb[m0 + mm];
            red[kg * 32 + j2] = dd;
            __syncthreads();
            if (t < 32) {
                float v = bpcv;
                #pragma unroll
                for (int g = 0; g < 8; g++) v += red[g * 32 + t];
                uint32_t sa = s2u(&llrl[rowbase + t]);
                #pragma unroll
                for (int r = 0; r < 8; r++) st_cluster_f(sa, (uint32_t)r, v);
                #pragma unroll
                for (int r = 0; r < 8; r++) mbar_arrive_cluster(mbarB, (uint32_t)r);
            }
            mbar_wait_cluster(mbarB, parB);
            parB ^= 1;
            if (t < 128) stack[idx * 128 + t] = llrl[t];
            else         stack[(idx + 1) * 128 + (t - 128)] = llrl[t];
            if (rank == 0 && t == 0) g_parRows[np] = op;
            np++; sp++;
            __syncthreads();
        } else {
            if (rank == 0 && t == 0) g_leafRows[nl] = op;
            nl++; sp--;
        }
        op++;
    }
    if (rank == 0 && t == 0) { g_nLeaf = nl; g_nPar = np; g_nOut = op; }
}

// ------------------- co1 (rows < nOut) + zero tail rows of out ----------------
__global__ void co1_zero(const float* __restrict__ b2, float* __restrict__ out) {
    __shared__ float hr[256];
    int r = blockIdx.x, t = threadIdx.x;
    if (r >= g_nOut) {
        float4* o = reinterpret_cast<float4*>(out + (long)r * VOCAB);
        float4 z = make_float4(0.f, 0.f, 0.f, 0.f);
        for (int i = t; i < VOCAB / 4; i += 256) o[i] = z;
        return;
    }
    hr[t] = g_H[r * 256 + t];
    __syncthreads();
    float a0 = 0.f, a1 = 0.f, a2 = 0.f, a3 = 0.f;
    #pragma unroll 4
    for (int k = 0; k < 256; k += 4) {
        a0 += g_W2T[(k + 0) * 256 + t] * hr[k + 0];
        a1 += g_W2T[(k + 1) * 256 + t] * hr[k + 1];
        a2 += g_W2T[(k + 2) * 256 + t] * hr[k + 2];
        a3 += g_W2T[(k + 3) * 256 + t] * hr[k + 3];
    }
    g_CO[r * 256 + t] = (a0 + a1) + (a2 + a3) + b2[1 + t];
}

// ------------------- value GEMM: f32x2 accumulators (R8 structure) ------------
__global__ void __launch_bounds__(256) value_gemm(const float* __restrict__ Wl,
                                                  const float* __restrict__ bl,
                                                  const float* __restrict__ Wp,
                                                  const float* __restrict__ bp,
                                                  float* __restrict__ out) {
    __shared__ __align__(16) float Cs[64 * 136];
    __shared__ int rs[128];
    int t = threadIdx.x;
    int which = blockIdx.y;
    int cnt = which ? g_nPar : g_nLeaf;
    if (cnt == 0) return;
    const float* W    = which ? Wp : Wl;
    const float* bias = which ? bp : bl;
    const int*  rows  = which ? g_parRows : g_leafRows;
    if (t < 128) rs[t] = (t < cnt) ? rows[t] : 0;

    int mlim = (cnt + 15) & ~15;
    int vi = t & 31, mi = t >> 5;
    bool active = (mi * 16) < cnt;
    int v0 = blockIdx.x * 128;

    unsigned long long acc[8][4];
    #pragma unroll
    for (int p = 0; p < 8; p++)
        #pragma unroll
        for (int c = 0; c < 4; c++) acc[p][c] = 0ull;

    const float* Wbase = W + (long)(v0 + vi * 4) * 256;

    for (int kc = 0; kc < 256; kc += 64) {
        __syncthreads();
        for (int idx = t; idx < 64 * mlim; idx += 256) {
            int k = idx & 63, m = idx >> 6;
            Cs[k * 136 + m] = (m < cnt) ? g_CO[rs[m] * 256 + kc + k] : 0.f;
        }
        __syncthreads();
        if (active) {
            #pragma unroll 2
            for (int k4 = 0; k4 < 64; k4 += 4) {
                float4 r0 = *reinterpret_cast<const float4*>(Wbase + 0 * 256 + kc + k4);
                float4 r1 = *reinterpret_cast<const float4*>(Wbase + 1 * 256 + kc + k4);
                float4 r2 = *reinterpret_cast<const float4*>(Wbase + 2 * 256 + kc + k4);
                float4 r3 = *reinterpret_cast<const float4*>(Wbase + 3 * 256 + kc + k4);
                float bw0[4] = {r0.x, r0.y, r0.z, r0.w};
                float bw1[4] = {r1.x, r1.y, r1.z, r1.w};
                float bw2[4] = {r2.x, r2.y, r2.z, r2.w};
                float bw3[4] = {r3.x, r3.y, r3.z, r3.w};
                #pragma unroll
                for (int kk = 0; kk < 4; kk++) {
                    const longlong2* ap = reinterpret_cast<const longlong2*>(
                        &Cs[(k4 + kk) * 136 + mi * 16]);
                    longlong2 q0 = ap[0], q1 = ap[1], q2 = ap[2], q3 = ap[3];
                    unsigned long long a[8] = {
                        (unsigned long long)q0.x, (unsigned long long)q0.y,
                        (unsigned long long)q1.x, (unsigned long long)q1.y,
                        (unsigned long long)q2.x, (unsigned long long)q2.y,
                        (unsigned long long)q3.x, (unsigned long long)q3.y };
                    unsigned long long c0 = pack2(bw0[kk]);
                    unsigned long long c1 = pack2(bw1[kk]);
                    unsigned long long c2 = pack2(bw2[kk]);
                    unsigned long long c3 = pack2(bw3[kk]);
                    #pragma unroll
                    for (int p = 0; p < 8; p++) {
                        ffma2(acc[p][0], a[p], c0);
                        ffma2(acc[p][1], a[p], c1);
                        ffma2(acc[p][2], a[p], c2);
                        ffma2(acc[p][3], a[p], c3);
                    }
                }
            }
        }
    }
    if (active) {
        float4 bb = *reinterpret_cast<const float4*>(bias + v0 + vi * 4);
        #pragma unroll
        for (int p = 0; p < 8; p++) {
            #pragma unroll
            for (int half = 0; half < 2; half++) {
                int m = mi * 16 + 2 * p + half;
                if (m < cnt) {
                    long ro = (long)rs[m] * VOCAB + v0 + vi * 4;
                    float2 f0 = *reinterpret_cast<float2*>(&acc[p][0]);
                    float2 f1 = *reinterpret_cast<float2*>(&acc[p][1]);
                    float2 f2 = *reinterpret_cast<float2*>(&acc[p][2]);
                    float2 f3 = *reinterpret_cast<float2*>(&acc[p][3]);
                    float v0v = half ? f0.y : f0.x;
                    float v1v = half ? f1.y : f1.x;
                    float v2v = half ? f2.y : f2.x;
                    float v3v = half ? f3.y : f3.x;
                    *reinterpret_cast<float4*>(out + ro) =
                        make_float4(v0v + bb.x, v1v + bb.y, v2v + bb.z, v3v + bb.w);
                }
            }
        }
    }
}

// ------------------- launch -------------------
extern "C" void kernel_launch(void* const* d_in, const int* in_sizes, int n_in,
                              void* d_out, int out_size) {
    const float* embed = (const float*)d_in[0];
    const float* Wpar  = (const float*)d_in[1];
    const float* bpar  = (const float*)d_in[2];
    const float* Wmu   = (const float*)d_in[3];
    const float* bmu   = (const float*)d_in[4];
    const float* Wlv   = (const float*)d_in[5];
    const float* blv   = (const float*)d_in[6];
    const float* W1    = (const float*)d_in[7];
    const float* b1    = (const float*)d_in[8];
    const float* W2    = (const float*)d_in[9];
    const float* b2    = (const float*)d_in[10];
    const float* Wl    = (const float*)d_in[11];
    const float* bl    = (const float*)d_in[12];
    const float* Wp    = (const float*)d_in[13];
    const float* bp    = (const float*)d_in[14];
    const float* eps   = (const float*)d_in[15];
    const int*   values= (const int*)d_in[16];
    float* out = (float*)d_out;

    cudaFuncSetAttribute(dec_cluster, cudaFuncAttributeMaxDynamicSharedMemorySize,
                         DEC_SMEM_BYTES);

    enc7_prep<<<dim3(64, 9), 256>>>(embed, values, Wpar, bpar, Wp, W2, b2, bp);
    enc_level<<<dim3(32, 8), 256>>>(embed, values, Wpar, bpar, 63);   // d=6
    enc_level<<<dim3(16, 8), 256>>>(embed, values, Wpar, bpar, 31);   // d=5
    dec_cluster<<<8, 256, DEC_SMEM_BYTES>>>(W1, b1, W2, b2, Wpar, bpar,
                                            embed, values, Wmu, bmu, Wlv, blv,
                                            eps, out);
    co1_zero<<<MAX_STEPS, 256>>>(b2, out);
    value_gemm<<<dim3(VOCAB / 128, 2), 256>>>(Wl, bl, Wp, bp, out);
}

// round 11
// speedup vs baseline: 1.0307x; 1.0307x over previous
#include <cuda_runtime.h>
#include <cstdint>

#define HIDDEN   256
#define LATENT   128
#define VOCAB    32000
#define MAX_LEN  64
#define MAX_STEPS 128
#define N_NODES  511
#define TAIL_NBLK 192

// ------------------- device scratch -------------------
__device__ __align__(16) float g_h[N_NODES * HIDDEN];
__device__ __align__(16) float g_W2T[HIDDEN * HIDDEN];   // [k][j], rows 1..256 of W2
__device__ __align__(16) float g_WpCT[HIDDEN * HIDDEN];  // [m][j]
__device__ __align__(16) float g_bpC[HIDDEN];
__device__ __align__(16) float g_z[LATENT];
__device__ __align__(16) float g_H[MAX_STEPS * HIDDEN];
__device__ __align__(16) float g_CO[MAX_STEPS * HIDDEN];
__device__ int g_leafRows[MAX_STEPS];
__device__ int g_parRows[MAX_STEPS];
__device__ int g_nLeaf;
__device__ int g_nPar;
__device__ int g_nOut;
__device__ int g_bar_cnt;                 // returns to 0 after every barrier
__device__ volatile unsigned g_bar_gen;   // monotonic generation

// ------------------- PTX helpers -------------------
__device__ __forceinline__ uint32_t s2u(const void* p) {
    uint32_t a;
    asm("{ .reg .u64 t; cvta.to.shared.u64 t, %1; cvt.u32.u64 %0, t; }" : "=r"(a) : "l"(p));
    return a;
}
__device__ __forceinline__ uint32_t ctarank() {
    uint32_t r; asm("mov.u32 %0, %%cluster_ctarank;" : "=r"(r)); return r;
}
__device__ __forceinline__ void st_cluster_f(uint32_t saddr, uint32_t rank, float v) {
    uint32_t ra;
    asm volatile("mapa.shared::cluster.u32 %0, %1, %2;" : "=r"(ra) : "r"(saddr), "r"(rank));
    asm volatile("st.shared::cluster.b32 [%0], %1;" :: "r"(ra), "r"(__float_as_uint(v)) : "memory");
}
__device__ __forceinline__ void mbar_init(uint32_t a, uint32_t cnt) {
    asm volatile("mbarrier.init.shared.b64 [%0], %1;" :: "r"(a), "r"(cnt) : "memory");
}
__device__ __forceinline__ void mbar_arrive_cluster(uint32_t a, uint32_t r) {
    asm volatile("{ .reg .b32 ra; mapa.shared::cluster.u32 ra, %0, %1;\n\t"
                 "mbarrier.arrive.release.cluster.shared::cluster.b64 _, [ra]; }"
                 :: "r"(a), "r"(r) : "memory");
}
__device__ __forceinline__ void mbar_wait_cluster(uint32_t a, uint32_t parity) {
    uint32_t done;
    asm volatile("{ .reg .pred p; mbarrier.try_wait.parity.acquire.cluster.shared::cta.b64 p, [%1], %2; selp.b32 %0,1,0,p; }"
                 : "=r"(done) : "r"(a), "r"(parity) : "memory");
    if (!done) {
        asm volatile("{ .reg .pred P1;\n"
                     "WL%=:\n\t"
                     "mbarrier.try_wait.parity.acquire.cluster.shared::cta.b64 P1, [%0], %1, 0x989680;\n\t"
                     "@P1 bra.uni WD%=;\n\t"
                     "bra.uni WL%=;\n"
                     "WD%=:\n}"
                     :: "r"(a), "r"(parity) : "memory");
    }
}
#define CLUSTER_SYNC() do { \
    asm volatile("barrier.cluster.arrive.aligned;" ::: "memory"); \
    asm volatile("barrier.cluster.wait.aligned;" ::: "memory"); \
} while (0)

// f32x2 packed helpers
__device__ __forceinline__ unsigned long long pack2(float v) {
    unsigned long long r;
    asm("mov.b64 %0, {%1, %1};" : "=l"(r) : "r"(__float_as_uint(v)));
    return r;
}
__device__ __forceinline__ void ffma2(unsigned long long& acc,
                                      unsigned long long a, unsigned long long b) {
    asm("fma.rn.f32x2 %0, %1, %2, %0;" : "+l"(acc) : "l"(a), "l"(b));
}

// ------------------- shared encoder pair body --------------------------------
__device__ __forceinline__ void enc_pair_body(
    const float* __restrict__ embed, const int* __restrict__ values,
    const float* __restrict__ Wpar, const float* __restrict__ bpar,
    int n0, bool two, int leafkids, int ys, float (*cat)[768], int t)
{
    #pragma unroll
    for (int ln = 0; ln < 2; ln++) {
        if (ln == 1 && !two) {
            cat[1][t] = 0.f; cat[1][256 + t] = 0.f; cat[1][512 + t] = 0.f;
        } else {
            int n = n0 + ln;
            cat[ln][t] = embed[(long)values[n] * 256 + t];
            int li = 2 * n + 1, ri = 2 * n + 2;
            if (leafkids) {
                cat[ln][256 + t] = embed[(long)values[li] * 256 + t];
                cat[ln][512 + t] = embed[(long)values[ri] * 256 + t];
            } else {
                cat[ln][256 + t] = __ldcg(&g_h[li * 256 + t]);
                cat[ln][512 + t] = __ldcg(&g_h[ri * 256 + t]);
            }
        }
    }
    __syncthreads();
    int w = t >> 5, l = t & 31;
    int j0 = ys * 32 + w * 4;
    const float4* W4 = reinterpret_cast<const float4*>(Wpar);
    const float4* c0 = reinterpret_cast<const float4*>(cat[0]);
    const float4* c1 = reinterpret_cast<const float4*>(cat[1]);
    float a0 = 0.f, a1 = 0.f, a2 = 0.f, a3 = 0.f;
    float b0 = 0.f, b1 = 0.f, b2v = 0.f, b3 = 0.f;
    #pragma unroll
    for (int it = 0; it < 6; it++) {
        int ki = it * 32 + l;
        float4 w0 = W4[(long)(j0 + 0) * 192 + ki];
        float4 w1 = W4[(long)(j0 + 1) * 192 + ki];
        float4 w2 = W4[(long)(j0 + 2) * 192 + ki];
        float4 w3 = W4[(long)(j0 + 3) * 192 + ki];
        float4 v0 = c0[ki];
        float4 v1 = c1[ki];
        a0 += w0.x * v0.x + w0.y * v0.y + w0.z * v0.z + w0.w * v0.w;
        a1 += w1.x * v0.x + w1.y * v0.y + w1.z * v0.z + w1.w * v0.w;
        a2 += w2.x * v0.x + w2.y * v0.y + w2.z * v0.z + w2.w * v0.w;
        a3 += w3.x * v0.x + w3.y * v0.y + w3.z * v0.z + w3.w * v0.w;
        b0 += w0.x * v1.x + w0.y * v1.y + w0.z * v1.z + w0.w * v1.w;
        b1 += w1.x * v1.x + w1.y * v1.y + w1.z * v1.z + w1.w * v1.w;
        b2v += w2.x * v1.x + w2.y * v1.y + w2.z * v1.z + w2.w * v1.w;
        b3 += w3.x * v1.x + w3.y * v1.y + w3.z * v1.z + w3.w * v1.w;
    }
    #pragma unroll
    for (int o = 16; o; o >>= 1) {
        a0 += __shfl_xor_sync(0xFFFFFFFFu, a0, o);
        a1 += __shfl_xor_sync(0xFFFFFFFFu, a1, o);
        a2 += __shfl_xor_sync(0xFFFFFFFFu, a2, o);
        a3 += __shfl_xor_sync(0xFFFFFFFFu, a3, o);
        b0 += __shfl_xor_sync(0xFFFFFFFFu, b0, o);
        b1 += __shfl_xor_sync(0xFFFFFFFFu, b1, o);
        b2v += __shfl_xor_sync(0xFFFFFFFFu, b2v, o);
        b3 += __shfl_xor_sync(0xFFFFFFFFu, b3, o);
    }
    if (l == 0) {
        float bb0 = bpar[j0], bb1 = bpar[j0 + 1], bb2 = bpar[j0 + 2], bb3 = bpar[j0 + 3];
        g_h[n0 * 256 + j0 + 0] = a0 + bb0;
        g_h[n0 * 256 + j0 + 1] = a1 + bb1;
        g_h[n0 * 256 + j0 + 2] = a2 + bb2;
        g_h[n0 * 256 + j0 + 3] = a3 + bb3;
        if (two) {
            g_h[(n0 + 1) * 256 + j0 + 0] = b0 + bb0;
            g_h[(n0 + 1) * 256 + j0 + 1] = b1 + bb1;
            g_h[(n0 + 1) * 256 + j0 + 2] = b2v + bb2;
            g_h[(n0 + 1) * 256 + j0 + 3] = b3 + bb3;
        }
    }
}

// ------------------- encoder big level (d=7,6): separate launch --------------
__global__ void __launch_bounds__(256) enc_level(
    const float* __restrict__ embed, const int* __restrict__ values,
    const float* __restrict__ Wpar, const float* __restrict__ bpar,
    int first, int count, int leafkids)
{
    __shared__ __align__(16) float cat[2][768];
    int n0 = first + blockIdx.x * 2;
    bool two = (n0 + 1 < first + count);
    enc_pair_body(embed, values, Wpar, bpar, n0, two, leafkids,
                  blockIdx.y, cat, threadIdx.x);
}

// ------------------- enc tail: levels d=5..0 + prep + latent, one kernel -----
__global__ void __launch_bounds__(256) enc_tail(
    const float* __restrict__ embed, const int* __restrict__ values,
    const float* __restrict__ Wpar, const float* __restrict__ bpar,
    const float* __restrict__ Wmu, const float* __restrict__ bmu,
    const float* __restrict__ Wlv, const float* __restrict__ blv,
    const float* __restrict__ eps, float* __restrict__ out,
    const float* __restrict__ Wp, const float* __restrict__ W2,
    const float* __restrict__ b2, const float* __restrict__ bp)
{
    __shared__ __align__(16) float sm[8 * 256 + 256];   // 2304 floats: fits prep AND cat
    float (*cat)[768] = reinterpret_cast<float (*)[768]>(sm);
    int t = threadIdx.x, b = blockIdx.x;
    unsigned gen0 = g_bar_gen;   // read before any barrier release is possible
    int nbar = 0;

    // ---- prep (blocks 128..191), concurrent with level d=5 ----
    if (b >= 128) {
        int pb = b - 128;
        if (pb >= 32) {
            int base = (pb - 32) * 2048;
            #pragma unroll
            for (int it = 0; it < 8; it++) {
                int i = base + it * 256 + t;
                int j = i >> 8, k = i & 255;
                g_W2T[k * 256 + j] = W2[(1 + j) * 256 + k];
            }
        } else {
            float (*wrows)[256] = reinterpret_cast<float (*)[256]>(sm);
            float* b2s = sm + 8 * 256;
            int j0 = pb * 8;
            for (int i = t; i < 8 * 256; i += 256) {
                int r = i >> 8, k = i & 255;
                wrows[r][k] = Wp[(long)(VOCAB + j0 + r) * HIDDEN + k];
            }
            b2s[t] = b2[1 + t];
            __syncthreads();
            float acc[8] = {0.f, 0.f, 0.f, 0.f, 0.f, 0.f, 0.f, 0.f};
            for (int k = 0; k < 256; k++) {
                float w2v = W2[(1 + k) * 256 + t];
                #pragma unroll
                for (int r = 0; r < 8; r++) acc[r] += wrows[r][k] * w2v;
            }
            #pragma unroll
            for (int r = 0; r < 8; r++) g_WpCT[t * 256 + j0 + r] = acc[r];
            int w = t >> 5, l = t & 31;
            float p = wrows[w][l] * b2s[l] + wrows[w][l + 32] * b2s[l + 32]
                    + wrows[w][l + 64] * b2s[l + 64] + wrows[w][l + 96] * b2s[l + 96]
                    + wrows[w][l + 128] * b2s[l + 128] + wrows[w][l + 160] * b2s[l + 160]
                    + wrows[w][l + 192] * b2s[l + 192] + wrows[w][l + 224] * b2s[l + 224];
            #pragma unroll
            for (int o = 16; o; o >>= 1) p += __shfl_xor_sync(0xFFFFFFFFu, p, o);
            if (l == 0) g_bpC[j0 + w] = p + bp[VOCAB + j0 + w];
            __syncthreads();
        }
    }

    // ---- levels d=5..0, parallel per level, spin barrier between ----
    for (int d = 5; d >= 0; d--) {
        int first = (1 << d) - 1, count = 1 << d;
        int npair = (count + 1) >> 1;
        if (b < npair * 8) {
            int n0 = first + (b >> 3) * 2;
            bool two = (n0 + 1 < first + count);
            enc_pair_body(embed, values, Wpar, bpar, n0, two, 0, b & 7, cat, t);
        }
        // grid barrier over TAIL_NBLK blocks
        if (t == 0) {
            __threadfence();
            nbar++;
            unsigned target = gen0 + (unsigned)nbar;
            int old = atomicAdd(&g_bar_cnt, 1);
            if (old == TAIL_NBLK - 1) {
                g_bar_cnt = 0;
                __threadfence();
                g_bar_gen = target;
            } else {
                while ((int)(g_bar_gen - target) < 0) __nanosleep(32);
            }
            __threadfence();
        }
        __syncthreads();
    }

    // ---- latent head (block 0) ----
    if (b == 0) {
        float* root = sm;
        float* mu_s = sm + 256;
        float* lv_s = sm + 384;
        root[t] = __ldcg(&g_h[t]);
        __syncthreads();
        if (t < 128) {
            float a = bmu[t];
            #pragma unroll 4
            for (int k = 0; k < 256; k++) a += Wmu[t * 256 + k] * root[k];
            mu_s[t] = a;
            out[(long)MAX_STEPS * VOCAB + t] = a;
        } else {
            int j = t - 128;
            float a = blv[j];
            #pragma unroll 4
            for (int k = 0; k < 256; k++) a += Wlv[j * 256 + k] * root[k];
            lv_s[j] = a;
            out[(long)MAX_STEPS * VOCAB + 128 + j] = a;
        }
        __syncthreads();
        if (t < 128) g_z[t] = mu_s[t] + eps[t] * expf(0.5f * lv_s[t]);
    }
}

// ------------------- decoder: 8-CTA cluster, mbarrier exchanges ---------------
#define DSM_W1    0
#define DSM_WPC   4096
#define DSM_STACK 12288
#define DSM_HB    20480
#define DSM_LLRL  20992
#define DSM_PP    21248
#define DSM_RED   21264
#define DSM_FLOATS 21520
#define DSM_MBAR_BYTE (DSM_FLOATS * 4)
#define DEC_SMEM_BYTES (DSM_MBAR_BYTE + 16)

__global__ void __cluster_dims__(8, 1, 1) __launch_bounds__(256, 1)
dec_cluster(const float* __restrict__ W1, const float* __restrict__ b1,
            const float* __restrict__ W2, const float* __restrict__ b2)
{
    extern __shared__ float S[];
    float* W1s   = S + DSM_W1;
    float* WpCs  = S + DSM_WPC;
    float* stack = S + DSM_STACK;
    float* hb2   = S + DSM_HB;
    float* llrl  = S + DSM_LLRL;
    float* pp    = S + DSM_PP;
    float* red   = S + DSM_RED;
    uint32_t smem_u = s2u(S);
    uint32_t mbarA = smem_u + DSM_MBAR_BYTE;
    uint32_t mbarB = mbarA + 8;

    int t = threadIdx.x;
    int j2 = t & 31, kg = t >> 5;
    uint32_t rank = ctarank();
    int rowbase = (int)rank * 32;

    for (int i = t; i < 4096; i += 256) {
        int jp = i >> 7, k = i & 127;
        W1s[k * 32 + jp] = W1[(rowbase + jp) * 128 + k];
    }
    for (int i = t; i < 8192; i += 256) {
        int m = i >> 5, jp = i & 31;
        WpCs[i] = g_WpCT[m * 256 + rowbase + jp];
    }
    for (int i = t; i < 8192; i += 256) stack[i] = 0.f;
    __syncthreads();
    if (t < 128) stack[t] = g_z[t];
    float b1v   = (t < 32) ? b1[rowbase + t] : 0.f;
    float bpcv  = (t < 32) ? g_bpC[rowbase + t] : 0.f;
    float w2r0v = (t < 32) ? W2[rowbase + t] : 0.f;
    float b20   = b2[0];
    if (t == 0) { mbar_init(mbarA, 256); mbar_init(mbarB, 256); }
    __syncthreads();
    CLUSTER_SYNC();

    int sp = 1, op = 0, nl = 0, np = 0;
    uint32_t parA = 0, parB = 0;
    for (int step = 0; step < MAX_STEPS && sp > 0; step++) {
        int idx = sp - 1;
        float* hb = hb2 + (step & 1) * 256;
        const float* x = stack + idx * 128;

        {
            float acc = 0.f;
            int k0 = kg * 16;
            #pragma unroll
            for (int kk = 0; kk < 16; kk++)
                acc += W1s[(k0 + kk) * 32 + j2] * x[k0 + kk];
            red[kg * 32 + j2] = acc;
        }
        __syncthreads();
        if (t < 32) {
            float v = b1v;
            #pragma unroll
            for (int g = 0; g < 8; g++) v += red[g * 32 + t];
            v = v > 0.f ? v : 0.2f * v;
            uint32_t sa = s2u(&hb[rowbase + t]);
            #pragma unroll
            for (int r = 0; r < 8; r++) st_cluster_f(sa, (uint32_t)r, v);
            g_H[op * 256 + rowbase + t] = v;
            float p = w2r0v * v;
            #pragma unroll
            for (int o = 16; o; o >>= 1) p += __shfl_xor_sync(0xFFFFFFFFu, p, o);
            if (t == 0) {
                uint32_t sb = s2u(&pp[(step & 1) * 8 + rank]);
                #pragma unroll
                for (int r = 0; r < 8; r++) st_cluster_f(sb, (uint32_t)r, p);
            }
            #pragma unroll
            for (int r = 0; r < 8; r++) mbar_arrive_cluster(mbarA, (uint32_t)r);
        }
        mbar_wait_cluster(mbarA, parA);
        parA ^= 1;
        const float* ppb = pp + (step & 1) * 8;
        float co0 = b20 + ((ppb[0] + ppb[1]) + (ppb[2] + ppb[3]))
                        + ((ppb[4] + ppb[5]) + (ppb[6] + ppb[7]));
        bool parent = (co0 > 0.f) && (idx <= MAX_LEN - 2);

        if (parent) {
            float dd = 0.f;
            int m0 = kg * 32;
            #pragma unroll
            for (int mm = 0; mm < 32; mm++)
                dd += WpCs[(m0 + mm) * 32 + j2] * hb[m0 + mm];
            red[kg * 32 + j2] = dd;
            __syncthreads();
            if (t < 32) {
                float v = bpcv;
                #pragma unroll
                for (int g = 0; g < 8; g++) v += red[g * 32 + t];
                uint32_t sa = s2u(&llrl[rowbase + t]);
                #pragma unroll
                for (int r = 0; r < 8; r++) st_cluster_f(sa, (uint32_t)r, v);
                #pragma unroll
                for (int r = 0; r < 8; r++) mbar_arrive_cluster(mbarB, (uint32_t)r);
            }
            mbar_wait_cluster(mbarB, parB);
            parB ^= 1;
            if (t < 128) stack[idx * 128 + t] = llrl[t];
            else         stack[(idx + 1) * 128 + (t - 128)] = llrl[t];
            if (rank == 0 && t == 0) g_parRows[np] = op;
            np++; sp++;
            __syncthreads();
        } else {
            if (rank == 0 && t == 0) g_leafRows[nl] = op;
            nl++; sp--;
        }
        op++;
    }
    if (rank == 0 && t == 0) { g_nLeaf = nl; g_nPar = np; g_nOut = op; }
}

// ------------------- co1 (rows < nOut) + zero tail rows of out ----------------
__global__ void co1_zero(const float* __restrict__ b2, float* __restrict__ out) {
    __shared__ float hr[256];
    int r = blockIdx.x, t = threadIdx.x;
    if (r >= g_nOut) {
        float4* o = reinterpret_cast<float4*>(out + (long)r * VOCAB);
        float4 z = make_float4(0.f, 0.f, 0.f, 0.f);
        for (int i = t; i < VOCAB / 4; i += 256) o[i] = z;
        return;
    }
    hr[t] = g_H[r * 256 + t];
    __syncthreads();
    float a0 = 0.f, a1 = 0.f, a2 = 0.f, a3 = 0.f;
    #pragma unroll 4
    for (int k = 0; k < 256; k += 4) {
        a0 += g_W2T[(k + 0) * 256 + t] * hr[k + 0];
        a1 += g_W2T[(k + 1) * 256 + t] * hr[k + 1];
        a2 += g_W2T[(k + 2) * 256 + t] * hr[k + 2];
        a3 += g_W2T[(k + 3) * 256 + t] * hr[k + 3];
    }
    g_CO[r * 256 + t] = (a0 + a1) + (a2 + a3) + b2[1 + t];
}

// ------------------- value GEMM: f32x2 accumulators (R8 structure) ------------
__global__ void __launch_bounds__(256) value_gemm(const float* __restrict__ Wl,
                                                  const float* __restrict__ bl,
                                                  const float* __restrict__ Wp,
                                                  const float* __restrict__ bp,
                                                  float* __restrict__ out) {
    __shared__ __align__(16) float Cs[64 * 136];
    __shared__ int rs[128];
    int t = threadIdx.x;
    int which = blockIdx.y;
    int cnt = which ? g_nPar : g_nLeaf;
    if (cnt == 0) return;
    const float* W    = which ? Wp : Wl;
    const float* bias = which ? bp : bl;
    const int*  rows  = which ? g_parRows : g_leafRows;
    if (t < 128) rs[t] = (t < cnt) ? rows[t] : 0;

    int mlim = (cnt + 15) & ~15;
    int vi = t & 31, mi = t >> 5;
    bool active = (mi * 16) < cnt;
    int v0 = blockIdx.x * 128;

    unsigned long long acc[8][4];
    #pragma unroll
    for (int p = 0; p < 8; p++)
        #pragma unroll
        for (int c = 0; c < 4; c++) acc[p][c] = 0ull;

    const float* Wbase = W + (long)(v0 + vi * 4) * 256;

    for (int kc = 0; kc < 256; kc += 64) {
        __syncthreads();
        for (int idx = t; idx < 64 * mlim; idx += 256) {
            int k = idx & 63, m = idx >> 6;
            Cs[k * 136 + m] = (m < cnt) ? g_CO[rs[m] * 256 + kc + k] : 0.f;
        }
        __syncthreads();
        if (active) {
            #pragma unroll 2
            for (int k4 = 0; k4 < 64; k4 += 4) {
                float4 r0 = *reinterpret_cast<const float4*>(Wbase + 0 * 256 + kc + k4);
                float4 r1 = *reinterpret_cast<const float4*>(Wbase + 1 * 256 + kc + k4);
                float4 r2 = *reinterpret_cast<const float4*>(Wbase + 2 * 256 + kc + k4);
                float4 r3 = *reinterpret_cast<const float4*>(Wbase + 3 * 256 + kc + k4);
                float bw0[4] = {r0.x, r0.y, r0.z, r0.w};
                float bw1[4] = {r1.x, r1.y, r1.z, r1.w};
                float bw2[4] = {r2.x, r2.y, r2.z, r2.w};
                float bw3[4] = {r3.x, r3.y, r3.z, r3.w};
                #pragma unroll
                for (int kk = 0; kk < 4; kk++) {
                    const longlong2* ap = reinterpret_cast<const longlong2*>(
                        &Cs[(k4 + kk) * 136 + mi * 16]);
                    longlong2 q0 = ap[0], q1 = ap[1], q2 = ap[2], q3 = ap[3];
                    unsigned long long a[8] = {
                        (unsigned long long)q0.x, (unsigned long long)q0.y,
                        (unsigned long long)q1.x, (unsigned long long)q1.y,
                        (unsigned long long)q2.x, (unsigned long long)q2.y,
                        (unsigned long long)q3.x, (unsigned long long)q3.y };
                    unsigned long long c0 = pack2(bw0[kk]);
                    unsigned long long c1 = pack2(bw1[kk]);
                    unsigned long long c2 = pack2(bw2[kk]);
                    unsigned long long c3 = pack2(bw3[kk]);
                    #pragma unroll
                    for (int p = 0; p < 8; p++) {
                        ffma2(acc[p][0], a[p], c0);
                        ffma2(acc[p][1], a[p], c1);
                        ffma2(acc[p][2], a[p], c2);
                        ffma2(acc[p][3], a[p], c3);
                    }
                }
            }
        }
    }
    if (active) {
        float4 bb = *reinterpret_cast<const float4*>(bias + v0 + vi * 4);
        #pragma unroll
        for (int p = 0; p < 8; p++) {
            #pragma unroll
            for (int half = 0; half < 2; half++) {
                int m = mi * 16 + 2 * p + half;
                if (m < cnt) {
                    long ro = (long)rs[m] * VOCAB + v0 + vi * 4;
                    float2 f0 = *reinterpret_cast<float2*>(&acc[p][0]);
                    float2 f1 = *reinterpret_cast<float2*>(&acc[p][1]);
                    float2 f2 = *reinterpret_cast<float2*>(&acc[p][2]);
                    float2 f3 = *reinterpret_cast<float2*>(&acc[p][3]);
                    float v0v = half ? f0.y : f0.x;
                    float v1v = half ? f1.y : f1.x;
                    float v2v = half ? f2.y : f2.x;
                    float v3v = half ? f3.y : f3.x;
                    *reinterpret_cast<float4*>(out + ro) =
                        make_float4(v0v + bb.x, v1v + bb.y, v2v + bb.z, v3v + bb.w);
                }
            }
        }
    }
}

// ------------------- launch -------------------
extern "C" void kernel_launch(void* const* d_in, const int* in_sizes, int n_in,
                              void* d_out, int out_size) {
    const float* embed = (const float*)d_in[0];
    const float* Wpar  = (const float*)d_in[1];
    const float* bpar  = (const float*)d_in[2];
    const float* Wmu   = (const float*)d_in[3];
    const float* bmu   = (const float*)d_in[4];
    const float* Wlv   = (const float*)d_in[5];
    const float* blv   = (const float*)d_in[6];
    const float* W1    = (const float*)d_in[7];
    const float* b1    = (const float*)d_in[8];
    const float* W2    = (const float*)d_in[9];
    const float* b2    = (const float*)d_in[10];
    const float* Wl    = (const float*)d_in[11];
    const float* bl    = (const float*)d_in[12];
    const float* Wp    = (const float*)d_in[13];
    const float* bp    = (const float*)d_in[14];
    const float* eps   = (const float*)d_in[15];
    const int*   values= (const int*)d_in[16];
    float* out = (float*)d_out;

    cudaFuncSetAttribute(dec_cluster, cudaFuncAttributeMaxDynamicSharedMemorySize,
                         DEC_SMEM_BYTES);

    enc_level<<<dim3(64, 8), 256>>>(embed, values, Wpar, bpar, 127, 256, 1); // d=7
    enc_level<<<dim3(32, 8), 256>>>(embed, values, Wpar, bpar, 63, 128, 0);  // d=6
    enc_tail<<<TAIL_NBLK, 256>>>(embed, values, Wpar, bpar, Wmu, bmu, Wlv, blv,
                                 eps, out, Wp, W2, b2, bp);
    dec_cluster<<<8, 256, DEC_SMEM_BYTES>>>(W1, b1, W2, b2);
    co1_zero<<<MAX_STEPS, 256>>>(b2, out);
    value_gemm<<<dim3(VOCAB / 128, 2), 256>>>(Wl, bl, Wp, bp, out);
}